// round 3
// baseline (speedup 1.0000x reference)
#include <cuda_runtime.h>
#include <cstdint>

#define HDIM 128
#define NMAX 100032          // 1563 * 64
#define GMAX 1024
#define NCLS 10
#define BN_EPS 1e-5
#define SLOPE 0.01f

// ---------------- device scratch (static, no allocation) ----------------
__device__ __align__(16) float  g_agg[(size_t)NMAX * HDIM];   // neighbor aggregation
__device__ __align__(16) float  g_t  [(size_t)NMAX * HDIM];   // intermediate u = leaky((X+agg)Wa+ba)
__device__ __align__(16) float  g_h  [(size_t)NMAX * HDIM];   // layer output (pre/post BN)
__device__ __align__(16) float  g_hg [GMAX * HDIM];           // pooled graph features
__device__ __align__(16) double g_stats[2 * HDIM];            // col sums / sumsq (double for accuracy)
__device__ __align__(16) float  g_coef [2 * HDIM];            // BN affine: a, c

__device__ __forceinline__ float lrelu(float x) { return x > 0.f ? x : SLOPE * x; }

// ---------------- zero scratch (agg + stats + hg) ----------------
__global__ void zero_kernel(int nf) {
    int idx    = blockIdx.x * blockDim.x + threadIdx.x;
    int stride = gridDim.x * blockDim.x;
    float4 z = make_float4(0.f, 0.f, 0.f, 0.f);
    float4* a4 = reinterpret_cast<float4*>(g_agg);
    int n4 = nf >> 2;
    for (int i = idx; i < n4; i += stride) a4[i] = z;
    float4* h4 = reinterpret_cast<float4*>(g_hg);
    for (int i = idx; i < (GMAX * HDIM) >> 2; i += stride) h4[i] = z;
    if (idx < 2 * HDIM) g_stats[idx] = 0.0;
}

// ---------------- edge scatter: agg[dst] += X[src], one warp per edge ----------------
// edge_index is int32 (JAX x64 disabled: jnp.int64 silently becomes int32)
__global__ void scatter_kernel(const float* __restrict__ Xext,
                               const int* __restrict__ src,
                               const int* __restrict__ dst,
                               int E, int use_gh) {
    int w = (blockIdx.x * blockDim.x + threadIdx.x) >> 5;
    if (w >= E) return;
    int lane = threadIdx.x & 31;
    const float* X = use_gh ? g_h : Xext;
    int s = src[w];
    int d = dst[w];
    float4 v = *reinterpret_cast<const float4*>(X + (size_t)s * HDIM + lane * 4);
    float* p = g_agg + (size_t)d * HDIM + lane * 4;
    asm volatile("red.global.add.v4.f32 [%0], {%1, %2, %3, %4};"
                 :: "l"(p), "f"(v.x), "f"(v.y), "f"(v.z), "f"(v.w)
                 : "memory");
}

// ---------------- fused GEMM: [N,128] @ [128,128] + bias, leaky ----------------
// MODE 0: A = X (+ g_agg), out = g_t                (first linear of GIN conv)
// MODE 1: A = g_t,          out = g_h, accumulate BN stats (second linear + outer leaky)
// Block: 256 threads, 64 rows x 128 cols, BK=16. warp = 8 rows, lane = 4 cols.
template<int MODE>
__global__ void __launch_bounds__(256)
gemm_kernel(const float* __restrict__ Xext,
            const float* __restrict__ W,
            const float* __restrict__ bias,
            int N, int use_gh) {
    __shared__ __align__(16) float As[16][72];       // [k][row], padded (72*4=288B rows, 16B-mult)
    __shared__ __align__(16) float Ws[16 * HDIM];    // [k][col]
    __shared__ float csum[HDIM];
    __shared__ float csq [HDIM];

    const int tid  = threadIdx.x;
    const int tcol = tid & 31;         // cols tcol*4 .. +3
    const int trow = tid >> 5;         // rows trow*8 .. +7
    const int row0 = blockIdx.x * 64;

    const float* X;
    if (MODE == 0) X = use_gh ? g_h : Xext;
    else           X = g_t;

    float acc[8][4];
#pragma unroll
    for (int i = 0; i < 8; i++)
#pragma unroll
        for (int j = 0; j < 4; j++) acc[i][j] = 0.f;

    const int lr = tid >> 2;           // load row 0..63
    const int lk = (tid & 3) * 4;      // load k offset 0,4,8,12

    for (int k0 = 0; k0 < HDIM; k0 += 16) {
        // A tile (transposed into smem), fusing X + agg for MODE 0
        float4 av = make_float4(0.f, 0.f, 0.f, 0.f);
        int grow = row0 + lr;
        if (grow < N) {
            av = *reinterpret_cast<const float4*>(X + (size_t)grow * HDIM + k0 + lk);
            if (MODE == 0) {
                float4 gv = *reinterpret_cast<const float4*>(g_agg + (size_t)grow * HDIM + k0 + lk);
                av.x += gv.x; av.y += gv.y; av.z += gv.z; av.w += gv.w;
            }
        }
        As[lk + 0][lr] = av.x;
        As[lk + 1][lr] = av.y;
        As[lk + 2][lr] = av.z;
        As[lk + 3][lr] = av.w;

        // W tile: 16 contiguous rows of W
        const float4* wsrc = reinterpret_cast<const float4*>(W + k0 * HDIM);
        float4* wdst = reinterpret_cast<float4*>(Ws);
        wdst[tid]       = wsrc[tid];
        wdst[tid + 256] = wsrc[tid + 256];
        __syncthreads();

#pragma unroll
        for (int kk = 0; kk < 16; kk++) {
            float4 w  = *reinterpret_cast<float4*>(&Ws[kk * HDIM + tcol * 4]);
            float4 a0 = *reinterpret_cast<float4*>(&As[kk][trow * 8]);
            float4 a1 = *reinterpret_cast<float4*>(&As[kk][trow * 8 + 4]);
            float a[8] = {a0.x, a0.y, a0.z, a0.w, a1.x, a1.y, a1.z, a1.w};
#pragma unroll
            for (int i = 0; i < 8; i++) {
                acc[i][0] += a[i] * w.x;
                acc[i][1] += a[i] * w.y;
                acc[i][2] += a[i] * w.z;
                acc[i][3] += a[i] * w.w;
            }
        }
        __syncthreads();
    }

    float4 bv = *reinterpret_cast<const float4*>(bias + tcol * 4);

    if (MODE == 0) {
#pragma unroll
        for (int i = 0; i < 8; i++) {
            int grow = row0 + trow * 8 + i;
            if (grow < N) {
                float4 o;
                o.x = lrelu(acc[i][0] + bv.x);
                o.y = lrelu(acc[i][1] + bv.y);
                o.z = lrelu(acc[i][2] + bv.z);
                o.w = lrelu(acc[i][3] + bv.w);
                *reinterpret_cast<float4*>(g_t + (size_t)grow * HDIM + tcol * 4) = o;
            }
        }
    } else {
        float s0[4] = {0.f, 0.f, 0.f, 0.f};
        float s1[4] = {0.f, 0.f, 0.f, 0.f};
#pragma unroll
        for (int i = 0; i < 8; i++) {
            int grow = row0 + trow * 8 + i;
            if (grow < N) {
                float4 o;
                o.x = lrelu(acc[i][0] + bv.x);
                o.y = lrelu(acc[i][1] + bv.y);
                o.z = lrelu(acc[i][2] + bv.z);
                o.w = lrelu(acc[i][3] + bv.w);
                *reinterpret_cast<float4*>(g_h + (size_t)grow * HDIM + tcol * 4) = o;
                s0[0] += o.x; s1[0] += o.x * o.x;
                s0[1] += o.y; s1[1] += o.y * o.y;
                s0[2] += o.z; s1[2] += o.z * o.z;
                s0[3] += o.w; s1[3] += o.w * o.w;
            }
        }
        if (tid < HDIM) { csum[tid] = 0.f; csq[tid] = 0.f; }
        __syncthreads();
#pragma unroll
        for (int j = 0; j < 4; j++) {
            atomicAdd(&csum[tcol * 4 + j], s0[j]);
            atomicAdd(&csq [tcol * 4 + j], s1[j]);
        }
        __syncthreads();
        if (tid < HDIM) {
            atomicAdd(&g_stats[tid],        (double)csum[tid]);
            atomicAdd(&g_stats[HDIM + tid], (double)csq[tid]);
        }
    }
}

// ---------------- BN coefficients: a = g/sqrt(var+eps), c = be - a*mean ----------------
__global__ void coef_kernel(const float* __restrict__ gamma,
                            const float* __restrict__ beta, int N) {
    int c = threadIdx.x;
    double mean = g_stats[c] / (double)N;
    double var  = g_stats[HDIM + c] / (double)N - mean * mean;
    float a = (float)((double)gamma[c] / sqrt(var + (double)BN_EPS));
    g_coef[c]        = a;
    g_coef[HDIM + c] = beta[c] - a * (float)mean;
}

// ---------------- BN apply in place on g_h ----------------
__global__ void bnapply_kernel(int nf) {
    int idx    = blockIdx.x * blockDim.x + threadIdx.x;
    int stride = gridDim.x * blockDim.x;
    float4* h4 = reinterpret_cast<float4*>(g_h);
    int n4 = nf >> 2;
    for (int i = idx; i < n4; i += stride) {
        int c4 = (i & 31) * 4;
        float4 a = *reinterpret_cast<float4*>(&g_coef[c4]);
        float4 c = *reinterpret_cast<float4*>(&g_coef[HDIM + c4]);
        float4 v = h4[i];
        v.x = a.x * v.x + c.x;
        v.y = a.y * v.y + c.y;
        v.z = a.z * v.z + c.z;
        v.w = a.w * v.w + c.w;
        h4[i] = v;
    }
}

// ---------------- pool: hg[batch[i]] += BN2(g_h[i]), one warp per node ----------------
// batch is int32 (JAX x64 disabled)
__global__ void pool_kernel(const int* __restrict__ batch, int N) {
    int i = (blockIdx.x * blockDim.x + threadIdx.x) >> 5;
    if (i >= N) return;
    int lane = threadIdx.x & 31;
    int g = batch[i];
    int c4 = lane * 4;
    float4 p = *reinterpret_cast<const float4*>(g_h + (size_t)i * HDIM + c4);
    float4 a = *reinterpret_cast<float4*>(&g_coef[c4]);
    float4 c = *reinterpret_cast<float4*>(&g_coef[HDIM + c4]);
    float4 v;
    v.x = a.x * p.x + c.x;
    v.y = a.y * p.y + c.y;
    v.z = a.z * p.z + c.z;
    v.w = a.w * p.w + c.w;
    float* dst = g_hg + (size_t)g * HDIM + c4;
    asm volatile("red.global.add.v4.f32 [%0], {%1, %2, %3, %4};"
                 :: "l"(dst), "f"(v.x), "f"(v.y), "f"(v.z), "f"(v.w)
                 : "memory");
}

// ---------------- head: per-graph MLP + log_softmax ----------------
__global__ void head_kernel(const float* __restrict__ fcW1, const float* __restrict__ fcb1,
                            const float* __restrict__ fcW2, const float* __restrict__ fcb2,
                            float* __restrict__ out) {
    __shared__ float s[HDIM];
    __shared__ float y[HDIM];
    __shared__ float z[NCLS];
    __shared__ float red2[2];
    int g = blockIdx.x;
    int j = threadIdx.x;

    s[j] = g_hg[g * HDIM + j];
    __syncthreads();

    float acc = fcb1[j];
#pragma unroll 8
    for (int k = 0; k < HDIM; k++) acc += s[k] * fcW1[k * HDIM + j];
    y[j] = lrelu(acc);
    __syncthreads();

    if (j < NCLS) {
        float acc2 = fcb2[j];
#pragma unroll 8
        for (int k = 0; k < HDIM; k++) acc2 += y[k] * fcW2[k * NCLS + j];
        z[j] = acc2;
    }
    __syncthreads();

    if (j == 0) {
        float m = z[0];
#pragma unroll
        for (int c = 1; c < NCLS; c++) m = fmaxf(m, z[c]);
        float se = 0.f;
#pragma unroll
        for (int c = 0; c < NCLS; c++) se += expf(z[c] - m);
        red2[0] = m;
        red2[1] = logf(se);
    }
    __syncthreads();
    if (j < NCLS) out[g * NCLS + j] = z[j] - red2[0] - red2[1];
}

// ---------------- launch ----------------
extern "C" void kernel_launch(void* const* d_in, const int* in_sizes, int n_in,
                              void* d_out, int out_size) {
    const float* x    = (const float*)d_in[0];
    const float* W1a  = (const float*)d_in[1];
    const float* b1a  = (const float*)d_in[2];
    const float* W1b  = (const float*)d_in[3];
    const float* b1b  = (const float*)d_in[4];
    const float* g1   = (const float*)d_in[5];
    const float* be1  = (const float*)d_in[6];
    const float* W2a  = (const float*)d_in[7];
    const float* b2a  = (const float*)d_in[8];
    const float* W2b  = (const float*)d_in[9];
    const float* b2b  = (const float*)d_in[10];
    const float* g2   = (const float*)d_in[11];
    const float* be2  = (const float*)d_in[12];
    const float* fcW1 = (const float*)d_in[13];
    const float* fcb1 = (const float*)d_in[14];
    const float* fcW2 = (const float*)d_in[15];
    const float* fcb2 = (const float*)d_in[16];
    const int* ei     = (const int*)d_in[17];   // int32! (JAX x64 disabled)
    const int* batch  = (const int*)d_in[18];   // int32!
    float* out = (float*)d_out;

    const int N = in_sizes[0] / HDIM;
    const int E = in_sizes[17] / 2;

    const int gemmBlocks = (N + 63) / 64;
    const int scatBlocks = (E + 7) / 8;     // 8 warps of 32 per block
    const int poolBlocks = (N + 7) / 8;

    // ---- layer 1 ----
    zero_kernel<<<1024, 256>>>(N * HDIM);
    scatter_kernel<<<scatBlocks, 256>>>(x, ei, ei + E, E, 0);
    gemm_kernel<0><<<gemmBlocks, 256>>>(x, W1a, b1a, N, 0);
    gemm_kernel<1><<<gemmBlocks, 256>>>(nullptr, W1b, b1b, N, 0);
    coef_kernel<<<1, HDIM>>>(g1, be1, N);
    bnapply_kernel<<<1024, 256>>>(N * HDIM);

    // ---- layer 2 ----
    zero_kernel<<<1024, 256>>>(N * HDIM);
    scatter_kernel<<<scatBlocks, 256>>>(nullptr, ei, ei + E, E, 1);
    gemm_kernel<0><<<gemmBlocks, 256>>>(nullptr, W2a, b2a, N, 1);
    gemm_kernel<1><<<gemmBlocks, 256>>>(nullptr, W2b, b2b, N, 0);
    coef_kernel<<<1, HDIM>>>(g2, be2, N);

    // ---- pool + head ----
    pool_kernel<<<poolBlocks, 256>>>(batch, N);
    head_kernel<<<GMAX, HDIM>>>(fcW1, fcb1, fcW2, fcb2, out);
}